// round 2
// baseline (speedup 1.0000x reference)
#include <cuda_runtime.h>
#include <math.h>
#include <stdint.h>

#define NCTA 128
#define B    32
#define TENC 400
#define ED   512
#define TDEC 800
#define DD   80
#define LS   1024
#define UN   128
#define KER  31
#define FIL  32
#define KP0  1664
#define NCH0 13
#define KP1  2048
#define NCH1 16

typedef unsigned long long ull;

// ---------------- device state (no allocations allowed) ----------------
__device__ float g_WT0[4096 * KP0];          // [cta][k/4][32cols][4]
__device__ float g_WT1[4096 * KP1];
__device__ float g_keys[B * TENC * UN];
__device__ float g_h0[2][B * LS];
__device__ float g_c0[B * LS];
__device__ float g_h1[2][B * LS];
__device__ float g_c1[B * LS];
__device__ float g_ctx[B * ED];
__device__ float g_align[B * TENC];
__device__ float g_scores[B * TENC];
__device__ float g_Wc[KER * UN];
__device__ float g_locb[UN];
__device__ unsigned g_flag[B];
__device__ unsigned g_bar_count;
__device__ volatile unsigned g_bar_gen;

// ---------------- helpers ----------------
__device__ __forceinline__ void ffma2(ull& c, ull a, ull b) {
    asm("fma.rn.f32x2 %0, %1, %2, %0;" : "+l"(c) : "l"(a), "l"(b));
}
__device__ __forceinline__ float2 u2f(ull v) {
    float2 r; asm("mov.b64 {%0,%1}, %2;" : "=f"(r.x), "=f"(r.y) : "l"(v)); return r;
}
__device__ __forceinline__ void cpa16(uint32_t d, const void* s) {
    asm volatile("cp.async.cg.shared.global [%0], [%1], 16;" :: "r"(d), "l"(s));
}
__device__ __forceinline__ void cpcommit() { asm volatile("cp.async.commit_group;"); }
__device__ __forceinline__ void cpwait1()  { asm volatile("cp.async.wait_group 1;"); }
__device__ __forceinline__ void cpwait0()  { asm volatile("cp.async.wait_group 0;"); }

__device__ __forceinline__ float sigf(float x) { return 1.f / (1.f + expf(-x)); }

__device__ __forceinline__ void grid_sync() {
    __threadfence();
    __syncthreads();
    if (threadIdx.x == 0) {
        unsigned gen = g_bar_gen;
        if (atomicAdd(&g_bar_count, 1u) == NCTA - 1) {
            g_bar_count = 0;
            __threadfence();
            g_bar_gen = gen + 1;
        } else {
            while (g_bar_gen == gen) __nanosleep(64);
        }
    }
    __syncthreads();
    __threadfence();
}

// ---------------- prefetch a 128-k chunk of x into smem ----------------
template <int L>
__device__ __forceinline__ void prefetch(int tid, float* xbuf, int kbase, int t,
                                         const float* __restrict__ dec,
                                         const float* __restrict__ aux,   // L0: ctx; L1: h0_cur
                                         const float* __restrict__ hp) {  // L0: h0_prev; L1: h1_prev
    #pragma unroll
    for (int it = 0; it < 4; it++) {
        int i4 = tid + it * 256;          // 0..1023
        int b  = i4 >> 5;
        int kq = i4 & 31;
        int kg = kbase + kq * 4;
        float* dptr = xbuf + b * 128 + kq * 4;
        uint32_t d = (uint32_t)__cvta_generic_to_shared(dptr);
        const float* s;
        if (L == 0) {
            if (kg < DD)                 s = dec + ((size_t)b * TDEC + t) * DD + kg;
            else if (kg < DD + ED)       s = aux + b * ED + (kg - DD);
            else if (kg < DD + ED + LS)  s = hp + b * LS + (kg - DD - ED);
            else { *(float4*)dptr = make_float4(0.f, 0.f, 0.f, 0.f); continue; }
        } else {
            if (kg < LS) s = aux + b * LS + kg;
            else         s = hp + b * LS + (kg - LS);
        }
        cpa16(d, s);
    }
}

// ---------------- one LSTM layer: GEMM + fused gates ----------------
template <int L>
__device__ __forceinline__ void lstm_layer(int cta, int tid, int t,
        const float* __restrict__ dec,
        const float* __restrict__ hp,    // h_prev of this layer
        const float* __restrict__ aux,   // L0: ctx; L1: h0_cur
        float* __restrict__ h_out, float* __restrict__ c_state,
        const float* __restrict__ bias,
        float* xs, float (*zb)[33]) {
    const int KPAD = (L == 0) ? KP0 : KP1;
    const int NCH  = (L == 0) ? NCH0 : NCH1;
    const float* WT = (L == 0) ? g_WT0 : g_WT1;
    const float* wbase = WT + (size_t)cta * 32 * KPAD;
    int cl = tid & 31;
    int b0 = (tid >> 5) * 4;

    ull acc[4][2];
    #pragma unroll
    for (int j = 0; j < 4; j++) { acc[j][0] = 0ull; acc[j][1] = 0ull; }

    prefetch<L>(tid, xs, 0, t, dec, aux, hp);
    cpcommit();
    for (int c = 0; c < NCH; c++) {
        if (c + 1 < NCH) {
            prefetch<L>(tid, xs + ((c + 1) & 1) * 4096, (c + 1) * 128, t, dec, aux, hp);
            cpcommit();
            cpwait1();
        } else {
            cpwait0();
        }
        __syncthreads();
        const float* xb  = xs + (c & 1) * 4096;
        const float* wch = wbase + (size_t)c * 32 * 128;
        #pragma unroll 4
        for (int q = 0; q < 32; q++) {
            ulonglong2 wv = *(const ulonglong2*)(wch + q * 128 + cl * 4);
            #pragma unroll
            for (int j = 0; j < 4; j++) {
                ulonglong2 xv = *(const ulonglong2*)(xb + (b0 + j) * 128 + q * 4);
                ffma2(acc[j][0], wv.x, xv.x);
                ffma2(acc[j][1], wv.y, xv.y);
            }
        }
        __syncthreads();
    }
    #pragma unroll
    for (int j = 0; j < 4; j++) {
        float2 lo = u2f(acc[j][0]), hi = u2f(acc[j][1]);
        zb[cl][b0 + j] = lo.x + lo.y + hi.x + hi.y;
    }
    __syncthreads();
    // gates: thread -> (unit j = tid>>5, batch b = tid&31)
    {
        int j = tid >> 5, b = tid & 31;
        int u = cta * 8 + j;
        float zi = zb[j][b]      + bias[u];
        float zf = zb[8 + j][b]  + bias[1024 + u];
        float zg = zb[16 + j][b] + bias[2048 + u];
        float zo = zb[24 + j][b] + bias[3072 + u];
        float co = c_state[b * LS + u];
        float cn = sigf(zf) * co + sigf(zi) * tanhf(zg);
        c_state[b * LS + u] = cn;
        h_out[b * LS + u] = sigf(zo) * tanhf(cn);
    }
    __syncthreads();
}

// ---------------- persistent kernel ----------------
__global__ void __launch_bounds__(256, 1) k_persist(
        const float* __restrict__ dec, const float* __restrict__ values,
        const float* __restrict__ Wq, const float* __restrict__ v_a,
        const float* __restrict__ b_a, const float* __restrict__ bias0,
        const float* __restrict__ bias1, float* __restrict__ e_out) {
    __shared__ float xs[2 * 4096];
    __shared__ float zb[32][33];
    __shared__ float pq_s[2][128];
    __shared__ float aS[132];
    __shared__ float spart[100][4];
    __shared__ float sS[400];
    __shared__ float aA[400];
    __shared__ float red[256];
    int cta = blockIdx.x, tid = threadIdx.x;

    for (int t = 0; t < TDEC; t++) {
        int pr = t & 1, cu = pr ^ 1;

        lstm_layer<0>(cta, tid, t, dec, g_h0[pr], g_ctx, g_h0[cu], g_c0, bias0, xs, zb);
        grid_sync();
        lstm_layer<1>(cta, tid, t, dec, g_h1[pr], g_h0[cu], g_h1[cu], g_c1, bias1, xs, zb);
        grid_sync();

        // ---- P3: pq + conv + scores (4 CTAs per batch, 100 positions each) ----
        {
            int b = cta >> 2, qq = cta & 3, t0 = qq * 100;
            int u = tid & 127, half = tid >> 7;
            const float* hb = g_h1[cu] + b * LS + half * 512;
            const float* wq = Wq + (size_t)(half * 512) * UN + u;
            float acc = 0.f;
            #pragma unroll 8
            for (int k = 0; k < 512; k++) acc += __ldcg(hb + k) * wq[(size_t)k * UN];
            pq_s[half][u] = acc;
            for (int i = tid; i < 130; i += 256) {
                int tg = t0 - 15 + i;
                aS[i] = (tg >= 0 && tg < TENC) ? __ldcg(&g_align[b * TENC + tg]) : 0.f;
            }
            __syncthreads();
            float pqu = pq_s[0][u] + pq_s[1][u] + b_a[u] + g_locb[u];
            float vau = v_a[u];
            float wc[KER];
            #pragma unroll
            for (int k = 0; k < KER; k++) wc[k] = g_Wc[k * UN + u];
            int wl = (tid >> 5) & 3, lane = tid & 31;
            for (int tt = 0; tt < 50; tt++) {
                int tl = half * 50 + tt;
                float s = g_keys[((size_t)b * TENC + t0 + tl) * UN + u] + pqu;
                #pragma unroll
                for (int k = 0; k < KER; k++) s += aS[tl + k] * wc[k];
                float r = vau * tanhf(s);
                #pragma unroll
                for (int o = 16; o; o >>= 1) r += __shfl_down_sync(0xffffffffu, r, o);
                if (lane == 0) spart[tl][wl] = r;
            }
            __syncthreads();
            if (tid < 100)
                g_scores[b * TENC + t0 + tid] =
                    spart[tid][0] + spart[tid][1] + spart[tid][2] + spart[tid][3];
            __threadfence();
            __syncthreads();
            if (tid == 0) atomicAdd(&g_flag[b], 1u);
        }

        // ---- P4: softmax + e_out + align + context (CTA b < 32) ----
        if (cta < B) {
            int b = cta;
            if (tid == 0) {
                unsigned target = 4u * (unsigned)(t + 1);
                while (*((volatile unsigned*)&g_flag[b]) < target) __nanosleep(32);
            }
            __syncthreads();
            __threadfence();
            float lm = -1e30f;
            for (int i = tid; i < TENC; i += 256) {
                float v = __ldcg(&g_scores[b * TENC + i]);
                sS[i] = v; lm = fmaxf(lm, v);
            }
            red[tid] = lm; __syncthreads();
            for (int o = 128; o; o >>= 1) { if (tid < o) red[tid] = fmaxf(red[tid], red[tid + o]); __syncthreads(); }
            float m = red[0]; __syncthreads();
            float ls = 0.f;
            for (int i = tid; i < TENC; i += 256) {
                float e = expf(sS[i] - m);
                aA[i] = e; ls += e;
            }
            red[tid] = ls; __syncthreads();
            for (int o = 128; o; o >>= 1) { if (tid < o) red[tid] += red[tid + o]; __syncthreads(); }
            float inv = 1.f / red[0]; __syncthreads();
            for (int i = tid; i < TENC; i += 256) {
                float a = aA[i] * inv;
                aA[i] = a;
                e_out[((size_t)b * TDEC + t) * TENC + i] = a;
                g_align[b * TENC + i] = __ldcg(&g_align[b * TENC + i]) + a;
            }
            __syncthreads();
            float ax = 0.f, ay = 0.f;
            const float* vp = values + ((size_t)b * TENC) * ED + tid * 2;
            #pragma unroll 4
            for (int tt = 0; tt < TENC; tt++) {
                float a = aA[tt];
                float2 v = *(const float2*)(vp + (size_t)tt * ED);
                ax += a * v.x; ay += a * v.y;
            }
            g_ctx[b * ED + tid * 2]     = ax;
            g_ctx[b * ED + tid * 2 + 1] = ay;
        }
        grid_sync();
    }
}

// ---------------- prep kernels ----------------
__global__ void k_zero() {
    int i = blockIdx.x * 256 + threadIdx.x;
    if (i < B * LS) {
        g_h0[0][i] = 0.f; g_h0[1][i] = 0.f;
        g_h1[0][i] = 0.f; g_h1[1][i] = 0.f;
        g_c0[i] = 0.f;    g_c1[i] = 0.f;
    }
    if (i < B * ED)   g_ctx[i] = 0.f;
    if (i < B * TENC) g_align[i] = 0.f;
    if (i < B)        g_flag[i] = 0u;
    if (i == 0) { g_bar_count = 0u; g_bar_gen = 0u; }
}

__global__ void k_prep(const float* __restrict__ ck, const float* __restrict__ cb,
                       const float* __restrict__ Wloc) {
    int i = blockIdx.x * 256 + threadIdx.x;
    if (i < KER * UN) {
        int k = i >> 7, u = i & 127;
        float s = 0.f;
        for (int f = 0; f < FIL; f++) s += ck[k * FIL + f] * Wloc[f * UN + u];
        g_Wc[i] = s;
    }
    if (i < UN) {
        float s = 0.f;
        for (int f = 0; f < FIL; f++) s += cb[f] * Wloc[f * UN + i];
        g_locb[i] = s;
    }
}

// weight transform: concat([W;U]) [kreal,4096] -> layout [cta][k/4][32cols][4]
__global__ void k_wt(int layer, const float* __restrict__ W, const float* __restrict__ U,
                     int ksplit, int kreal, int kpad) {
    size_t o = (size_t)blockIdx.x * 256 + threadIdx.x;
    size_t total = (size_t)4096 * kpad;
    if (o >= total) return;
    float* dst = layer ? g_WT1 : g_WT0;
    int per = 32 * kpad;
    int c   = (int)(o / per);
    int r   = (int)(o % per);
    int kq  = r >> 7;
    int rem = r & 127;
    int cl  = rem >> 2, kl = rem & 3;
    int k   = kq * 4 + kl;
    int gate = cl >> 3, j = cl & 7;
    int col  = gate * 1024 + c * 8 + j;
    float v = 0.f;
    if (k < ksplit)      v = W[(size_t)k * 4096 + col];
    else if (k < kreal)  v = U[(size_t)(k - ksplit) * 4096 + col];
    dst[o] = v;
}

// keys = values @ Wm
__global__ void k_keys(const float* __restrict__ values, const float* __restrict__ Wm) {
    int b = blockIdx.x, t0 = blockIdx.y * 50;
    __shared__ float vs[10][ED];
    int u = threadIdx.x;
    for (int g = 0; g < 5; g++) {
        int tb = t0 + g * 10;
        __syncthreads();
        for (int i = u; i < 10 * ED; i += 128) {
            int tt = i >> 9, d = i & 511;
            vs[tt][d] = values[((size_t)b * TENC + tb + tt) * ED + d];
        }
        __syncthreads();
        float acc[10];
        #pragma unroll
        for (int tt = 0; tt < 10; tt++) acc[tt] = 0.f;
        for (int d = 0; d < ED; d++) {
            float w = Wm[d * UN + u];
            #pragma unroll
            for (int tt = 0; tt < 10; tt++) acc[tt] += vs[tt][d] * w;
        }
        #pragma unroll
        for (int tt = 0; tt < 10; tt++)
            g_keys[((size_t)b * TENC + tb + tt) * UN + u] = acc[tt];
    }
}

// c_outputs = e_outputs @ values
__global__ void k_final(const float* __restrict__ values, const float* __restrict__ e_out,
                        float* __restrict__ c_out) {
    int qt = blockIdx.x, b = blockIdx.y;
    int tid = threadIdx.x;
    __shared__ float es[8][100];
    float accx[8], accy[8];
    #pragma unroll
    for (int q = 0; q < 8; q++) { accx[q] = 0.f; accy[q] = 0.f; }
    for (int tc = 0; tc < 4; tc++) {
        __syncthreads();
        for (int i = tid; i < 800; i += 256) {
            int q = i / 100, tl = i - q * 100;
            es[q][tl] = e_out[((size_t)b * TDEC + qt * 8 + q) * TENC + tc * 100 + tl];
        }
        __syncthreads();
        for (int tl = 0; tl < 100; tl++) {
            float2 v = *(const float2*)(values + ((size_t)b * TENC + tc * 100 + tl) * ED + tid * 2);
            #pragma unroll
            for (int q = 0; q < 8; q++) {
                float e = es[q][tl];
                accx[q] += e * v.x;
                accy[q] += e * v.y;
            }
        }
    }
    #pragma unroll
    for (int q = 0; q < 8; q++) {
        size_t idx = ((size_t)b * TDEC + qt * 8 + q) * ED + tid * 2;
        c_out[idx]     = accx[q];
        c_out[idx + 1] = accy[q];
    }
}

// ---------------- launch ----------------
extern "C" void kernel_launch(void* const* d_in, const int* in_sizes, int n_in,
                              void* d_out, int out_size) {
    const float* values = (const float*)d_in[0];
    const float* dec    = (const float*)d_in[1];
    const float* Wm     = (const float*)d_in[2];
    const float* Wq     = (const float*)d_in[3];
    const float* convk  = (const float*)d_in[4];
    const float* convb  = (const float*)d_in[5];
    const float* Wloc   = (const float*)d_in[6];
    const float* v_a    = (const float*)d_in[7];
    const float* b_a    = (const float*)d_in[8];
    const float* W0     = (const float*)d_in[9];
    const float* U0     = (const float*)d_in[10];
    const float* b0     = (const float*)d_in[11];
    const float* W1     = (const float*)d_in[12];
    const float* U1     = (const float*)d_in[13];
    const float* b1     = (const float*)d_in[14];

    float* out   = (float*)d_out;
    float* c_out = out;                              // [B, TDEC, ED]
    float* e_out = out + (size_t)B * TDEC * ED;      // [B, TDEC, TENC]

    k_zero<<<128, 256>>>();
    k_prep<<<16, 256>>>(convk, convb, Wloc);
    {
        size_t n0 = (size_t)4096 * KP0;
        size_t n1 = (size_t)4096 * KP1;
        k_wt<<<(unsigned)((n0 + 255) / 256), 256>>>(0, W0, U0, DD + ED, DD + ED + LS, KP0);
        k_wt<<<(unsigned)((n1 + 255) / 256), 256>>>(1, W1, U1, LS, 2 * LS, KP1);
    }
    k_keys<<<dim3(B, 8), 128>>>(values, Wm);

    k_persist<<<NCTA, 256>>>(dec, values, Wq, v_a, b_a, b0, b1, e_out);

    k_final<<<dim3(100, B), 256>>>(values, e_out, c_out);
}

// round 3
// speedup vs baseline: 1.8479x; 1.8479x over previous
#include <cuda_runtime.h>
#include <math.h>
#include <stdint.h>

#define NCTA 128
#define B    32
#define TENC 400
#define ED   512
#define TDEC 800
#define DD   80
#define LS   1024
#define UN   128
#define KER  31
#define FIL  32

#define KCH   256
#define NCH0  7          // K0 padded to 1792
#define K0REAL 1616
#define NCH1  8          // K1 = 2048
#define SROW  264        // bf16 row stride (elems), 528B
#define XFROW 260        // f32 staging row stride

// ---- dynamic smem layout (bytes) ----
#define OFF_W     0          // 2 x (WH 16896 + WL 16896) = 67584
#define WBUF_SZ   33792
#define OFF_XF    67584      // 32*260*4 = 33280
#define OFF_XH    100864     // 16896
#define OFF_XL    117760     // 16896
#define OFF_ZSM   134656     // 2*32*33*4 = 8448
#define OFF_PQ    143104     // 1024
#define OFF_AS    144128     // 544
#define OFF_SPART 144672     // 1600
#define OFF_SS    146272     // 1600
#define OFF_AA    147872     // 1600
#define OFF_RED   149472     // 1024
#define OFF_RED2  150496     // 1024
#define SMEM_TOTAL 151552

// ---------------- device state ----------------
__device__ unsigned short g_Wh0[128 * NCH0 * 32 * 256];
__device__ unsigned short g_Wl0[128 * NCH0 * 32 * 256];
__device__ unsigned short g_Wh1[128 * NCH1 * 32 * 256];
__device__ unsigned short g_Wl1[128 * NCH1 * 32 * 256];
__device__ float g_keys[B * TENC * UN];
__device__ float g_h0[2][B * LS];
__device__ float g_c0[B * LS];
__device__ float g_h1[2][B * LS];
__device__ float g_c1[B * LS];
__device__ float g_ctx[B * ED];
__device__ float g_align[B * TENC];
__device__ float g_scores[B * TENC];
__device__ float g_Wc[KER * UN];
__device__ float g_locb[UN];
__device__ unsigned g_flag[B];
__device__ unsigned g_bar_count;
__device__ volatile unsigned g_bar_gen;

// ---------------- helpers ----------------
__device__ __forceinline__ void cpa16(uint32_t d, const void* s) {
    asm volatile("cp.async.cg.shared.global [%0], [%1], 16;" :: "r"(d), "l"(s));
}
__device__ __forceinline__ void cpcommit() { asm volatile("cp.async.commit_group;"); }
__device__ __forceinline__ void cpwait0()  { asm volatile("cp.async.wait_group 0;"); }

__device__ __forceinline__ void ldsm4(uint32_t a, uint32_t& r0, uint32_t& r1,
                                      uint32_t& r2, uint32_t& r3) {
    asm volatile("ldmatrix.sync.aligned.m8n8.x4.shared.b16 {%0,%1,%2,%3}, [%4];"
                 : "=r"(r0), "=r"(r1), "=r"(r2), "=r"(r3) : "r"(a));
}
__device__ __forceinline__ void ldsm2(uint32_t a, uint32_t& r0, uint32_t& r1) {
    asm volatile("ldmatrix.sync.aligned.m8n8.x2.shared.b16 {%0,%1}, [%2];"
                 : "=r"(r0), "=r"(r1) : "r"(a));
}
__device__ __forceinline__ void mma16816(float* c, uint32_t a0, uint32_t a1,
                                         uint32_t a2, uint32_t a3,
                                         uint32_t b0, uint32_t b1) {
    asm volatile("mma.sync.aligned.m16n8k16.row.col.f32.bf16.bf16.f32 "
                 "{%0,%1,%2,%3},{%4,%5,%6,%7},{%8,%9},{%0,%1,%2,%3};"
                 : "+f"(c[0]), "+f"(c[1]), "+f"(c[2]), "+f"(c[3])
                 : "r"(a0), "r"(a1), "r"(a2), "r"(a3), "r"(b0), "r"(b1));
}

__device__ __forceinline__ float sigf(float x) { return 1.f / (1.f + expf(-x)); }

__device__ __forceinline__ void grid_sync() {
    __threadfence();
    __syncthreads();
    if (threadIdx.x == 0) {
        unsigned gen = g_bar_gen;
        if (atomicAdd(&g_bar_count, 1u) == NCTA - 1) {
            g_bar_count = 0;
            __threadfence();
            g_bar_gen = gen + 1;
        } else {
            while (g_bar_gen == gen) __nanosleep(64);
        }
    }
    __syncthreads();
    __threadfence();
}

// ---------------- prefetchers ----------------
__device__ __forceinline__ void prefW(char* sm, int buf, int tid,
                                      const unsigned short* srcH,
                                      const unsigned short* srcL,
                                      int cta, int nch, int ch) {
    const unsigned short* sH = srcH + ((size_t)(cta * nch + ch) * 32) * 256;
    const unsigned short* sL = srcL + ((size_t)(cta * nch + ch) * 32) * 256;
    char* dH = sm + OFF_W + buf * WBUF_SZ;
    char* dL = dH + 16896;
    #pragma unroll
    for (int it = 0; it < 4; it++) {
        int idx = tid + it * 256;
        int n = idx >> 5, seg = idx & 31;
        uint32_t off = (uint32_t)(n * 528 + seg * 16);
        cpa16((uint32_t)__cvta_generic_to_shared(dH + off), sH + n * 256 + seg * 8);
        cpa16((uint32_t)__cvta_generic_to_shared(dL + off), sL + n * 256 + seg * 8);
    }
}

template <int L>
__device__ __forceinline__ void prefX(char* sm, int tid, int ch, int t,
                                      const float* __restrict__ dec,
                                      const float* __restrict__ ctx,
                                      const float* __restrict__ hA,
                                      const float* __restrict__ hB) {
    float* xf = (float*)(sm + OFF_XF);
    #pragma unroll
    for (int it = 0; it < 8; it++) {
        int idx = tid + it * 256;                  // 0..2047
        int b = idx >> 6, seg = idx & 63;
        int kg = ch * KCH + seg * 4;
        const float* s;
        if (L == 0) {
            if (kg < DD)            s = dec + ((size_t)b * TDEC + t) * DD + kg;
            else if (kg < DD + ED)  s = ctx + b * ED + (kg - DD);
            else if (kg < K0REAL)   s = hA + b * LS + (kg - DD - ED);
            else continue;
        } else {
            if (kg < LS) s = hA + b * LS + kg;
            else         s = hB + b * LS + (kg - LS);
        }
        cpa16((uint32_t)__cvta_generic_to_shared(xf + b * XFROW + seg * 4), s);
    }
}

template <int KREAL>
__device__ __forceinline__ void convX(char* sm, int tid, int ch) {
    float* xf = (float*)(sm + OFF_XF);
    unsigned short* xh = (unsigned short*)(sm + OFF_XH);
    unsigned short* xl = (unsigned short*)(sm + OFF_XL);
    int b = tid >> 3, q8 = tid & 7;
    #pragma unroll
    for (int i = 0; i < 8; i++) {
        int kloc = q8 * 32 + i * 4;
        int kg = ch * KCH + kloc;
        float4 v;
        if (kg < KREAL) v = *(const float4*)(xf + b * XFROW + kloc);
        else            v = make_float4(0.f, 0.f, 0.f, 0.f);
        unsigned hp0, hp1, lp0, lp1;
        asm("cvt.rn.bf16x2.f32 %0, %1, %2;" : "=r"(hp0) : "f"(v.y), "f"(v.x));
        asm("cvt.rn.bf16x2.f32 %0, %1, %2;" : "=r"(hp1) : "f"(v.w), "f"(v.z));
        float r0 = __uint_as_float(hp0 << 16);
        float r1 = __uint_as_float(hp0 & 0xffff0000u);
        float r2 = __uint_as_float(hp1 << 16);
        float r3 = __uint_as_float(hp1 & 0xffff0000u);
        float l0 = v.x - r0, l1 = v.y - r1, l2 = v.z - r2, l3 = v.w - r3;
        asm("cvt.rn.bf16x2.f32 %0, %1, %2;" : "=r"(lp0) : "f"(l1), "f"(l0));
        asm("cvt.rn.bf16x2.f32 %0, %1, %2;" : "=r"(lp1) : "f"(l3), "f"(l2));
        *(uint2*)(xh + b * SROW + kloc) = make_uint2(hp0, hp1);
        *(uint2*)(xl + b * SROW + kloc) = make_uint2(lp0, lp1);
    }
}

// ---------------- one LSTM layer ----------------
template <int L, int NCH, int KREAL>
__device__ void lstm_layer(char* sm, int cta, int tid, int t,
                           const float* __restrict__ dec,
                           const float* __restrict__ ctx,
                           const float* __restrict__ hA,
                           const float* __restrict__ hB,
                           float* __restrict__ h_out, float* __restrict__ c_state,
                           const float* __restrict__ bias,
                           const unsigned short* gWh, const unsigned short* gWl) {
    int lane = tid & 31, warp = tid >> 5;
    int nt = warp & 3, kh = warp >> 2;
    int n0 = nt * 8;
    uint32_t xh32 = (uint32_t)__cvta_generic_to_shared(sm + OFF_XH);
    uint32_t xl32 = (uint32_t)__cvta_generic_to_shared(sm + OFF_XL);
    uint32_t aoff = (uint32_t)((lane & 15) * 528 + (lane >> 4) * 16 + kh * 256);
    uint32_t boff = (uint32_t)((n0 + (lane & 7)) * 528 + ((lane >> 3) & 1) * 16 + kh * 256);

    float c[2][4];
    #pragma unroll
    for (int mt = 0; mt < 2; mt++)
        #pragma unroll
        for (int j = 0; j < 4; j++) c[mt][j] = 0.f;

    prefW(sm, 0, tid, gWh, gWl, cta, NCH, 0);
    prefX<L>(sm, tid, 0, t, dec, ctx, hA, hB);
    cpcommit();

    for (int ch = 0; ch < NCH; ch++) {
        cpwait0();
        __syncthreads();
        convX<KREAL>(sm, tid, ch);
        __syncthreads();
        if (ch + 1 < NCH) {
            prefW(sm, (ch + 1) & 1, tid, gWh, gWl, cta, NCH, ch + 1);
            prefX<L>(sm, tid, ch + 1, t, dec, ctx, hA, hB);
            cpcommit();
        }
        uint32_t wh32 = (uint32_t)__cvta_generic_to_shared(sm + OFF_W + (ch & 1) * WBUF_SZ);
        uint32_t wl32 = wh32 + 16896;
        #pragma unroll
        for (int kk = 0; kk < 8; kk++) {
            uint32_t kb = kk * 32;
            uint32_t b0, b1, f0, f1;
            ldsm2(wh32 + boff + kb, b0, b1);
            ldsm2(wl32 + boff + kb, f0, f1);
            uint32_t a0, a1, a2, a3, e0, e1, e2, e3;
            ldsm4(xh32 + aoff + kb, a0, a1, a2, a3);
            ldsm4(xl32 + aoff + kb, e0, e1, e2, e3);
            mma16816(c[0], a0, a1, a2, a3, b0, b1);
            mma16816(c[0], a0, a1, a2, a3, f0, f1);
            mma16816(c[0], e0, e1, e2, e3, b0, b1);
            ldsm4(xh32 + aoff + kb + 16 * 528, a0, a1, a2, a3);
            ldsm4(xl32 + aoff + kb + 16 * 528, e0, e1, e2, e3);
            mma16816(c[1], a0, a1, a2, a3, b0, b1);
            mma16816(c[1], a0, a1, a2, a3, f0, f1);
            mma16816(c[1], e0, e1, e2, e3, b0, b1);
        }
    }

    float* zsm = (float*)(sm + OFF_ZSM);
    {
        int r = lane >> 2, cp = (lane & 3) * 2;
        float* zz = zsm + kh * (32 * 33);
        #pragma unroll
        for (int mt = 0; mt < 2; mt++) {
            int row = mt * 16 + r;
            zz[row * 33 + n0 + cp]           = c[mt][0];
            zz[row * 33 + n0 + cp + 1]       = c[mt][1];
            zz[(row + 8) * 33 + n0 + cp]     = c[mt][2];
            zz[(row + 8) * 33 + n0 + cp + 1] = c[mt][3];
        }
    }
    __syncthreads();
    {
        int j = tid >> 5, b = tid & 31;
        int u = cta * 8 + j;
        float z[4];
        #pragma unroll
        for (int g = 0; g < 4; g++) {
            int n = g * 8 + j;
            z[g] = zsm[b * 33 + n] + zsm[32 * 33 + b * 33 + n] + bias[g * 1024 + u];
        }
        float co = c_state[b * LS + u];
        float cn = sigf(z[1]) * co + sigf(z[0]) * tanhf(z[2]);
        c_state[b * LS + u] = cn;
        h_out[b * LS + u] = sigf(z[3]) * tanhf(cn);
    }
    __syncthreads();
}

// ---------------- persistent kernel ----------------
__global__ void __launch_bounds__(256, 1) k_persist(
        const float* __restrict__ dec, const float* __restrict__ values,
        const float* __restrict__ Wq, const float* __restrict__ v_a,
        const float* __restrict__ b_a, const float* __restrict__ bias0,
        const float* __restrict__ bias1,
        float* __restrict__ e_out, float* __restrict__ c_out) {
    extern __shared__ char sm[];
    int cta = blockIdx.x, tid = threadIdx.x;

    float* pq_s  = (float*)(sm + OFF_PQ);     // [2][128]
    float* aS    = (float*)(sm + OFF_AS);     // [132]
    float* spart = (float*)(sm + OFF_SPART);  // [100][4]
    float* sS    = (float*)(sm + OFF_SS);     // [400]
    float* aA    = (float*)(sm + OFF_AA);     // [400]
    float* red   = (float*)(sm + OFF_RED);    // [256]
    float* red2  = (float*)(sm + OFF_RED2);   // [256]

    for (int t = 0; t < TDEC; t++) {
        int pr = t & 1, cu = pr ^ 1;

        lstm_layer<0, NCH0, K0REAL>(sm, cta, tid, t, dec, g_ctx, g_h0[pr], g_h0[pr],
                                    g_h0[cu], g_c0, bias0, g_Wh0, g_Wl0);
        grid_sync();
        lstm_layer<1, NCH1, 2048>(sm, cta, tid, t, dec, g_ctx, g_h0[cu], g_h1[pr],
                                  g_h1[cu], g_c1, bias1, g_Wh1, g_Wl1);
        grid_sync();

        // ---- P3: pq + location conv + scores (4 CTAs per batch) ----
        {
            int b = cta >> 2, qq = cta & 3, t0 = qq * 100;
            int u = tid & 127, half = tid >> 7;
            const float* hb = g_h1[cu] + b * LS + half * 512;
            const float* wq = Wq + (size_t)(half * 512) * UN + u;
            float acc = 0.f;
            #pragma unroll 8
            for (int k = 0; k < 512; k++) acc += __ldcg(hb + k) * wq[(size_t)k * UN];
            pq_s[half * 128 + u] = acc;
            for (int i = tid; i < 130; i += 256) {
                int tg = t0 - 15 + i;
                aS[i] = (tg >= 0 && tg < TENC) ? __ldcg(&g_align[b * TENC + tg]) : 0.f;
            }
            __syncthreads();
            float pqu = pq_s[u] + pq_s[128 + u] + b_a[u] + g_locb[u];
            float vau = v_a[u];
            float wc[KER];
            #pragma unroll
            for (int k = 0; k < KER; k++) wc[k] = g_Wc[k * UN + u];
            int wl = (tid >> 5) & 3, lane = tid & 31;
            for (int tt = 0; tt < 50; tt++) {
                int tl = half * 50 + tt;
                float s = g_keys[((size_t)b * TENC + t0 + tl) * UN + u] + pqu;
                #pragma unroll
                for (int k = 0; k < KER; k++) s += aS[tl + k] * wc[k];
                float r = vau * tanhf(s);
                #pragma unroll
                for (int o = 16; o; o >>= 1) r += __shfl_down_sync(0xffffffffu, r, o);
                if (lane == 0) spart[tl * 4 + wl] = r;
            }
            __syncthreads();
            if (tid < 100)
                g_scores[b * TENC + t0 + tid] =
                    spart[tid * 4] + spart[tid * 4 + 1] + spart[tid * 4 + 2] + spart[tid * 4 + 3];
            __threadfence();
            __syncthreads();
            if (tid == 0) atomicAdd(&g_flag[b], 1u);
        }

        // ---- P4: softmax (x4 redundant) + e_out/align (qq==0) + context d-slice ----
        {
            int b = cta >> 2, qq = cta & 3;
            if (tid == 0) {
                unsigned target = 4u * (unsigned)(t + 1);
                while (*((volatile unsigned*)&g_flag[b]) < target) __nanosleep(32);
            }
            __syncthreads();
            __threadfence();
            float lm = -1e30f;
            for (int i = tid; i < TENC; i += 256) {
                float v = __ldcg(&g_scores[b * TENC + i]);
                sS[i] = v; lm = fmaxf(lm, v);
            }
            red[tid] = lm; __syncthreads();
            for (int o = 128; o; o >>= 1) { if (tid < o) red[tid] = fmaxf(red[tid], red[tid + o]); __syncthreads(); }
            float m = red[0]; __syncthreads();
            float ls = 0.f;
            for (int i = tid; i < TENC; i += 256) {
                float e = expf(sS[i] - m);
                aA[i] = e; ls += e;
            }
            red[tid] = ls; __syncthreads();
            for (int o = 128; o; o >>= 1) { if (tid < o) red[tid] += red[tid + o]; __syncthreads(); }
            float inv = 1.f / red[0]; __syncthreads();
            for (int i = tid; i < TENC; i += 256) aA[i] *= inv;
            __syncthreads();
            if (qq == 0) {
                for (int i = tid; i < TENC; i += 256) {
                    e_out[((size_t)b * TDEC + t) * TENC + i] = aA[i];
                    g_align[b * TENC + i] += aA[i];
                }
            }
            // context slice [qq*128, qq*128+128)
            int dl = tid & 127, th = tid >> 7;
            int d = qq * 128 + dl;
            float acc = 0.f;
            const float* vp = values + ((size_t)b * TENC + th * 200) * ED + d;
            #pragma unroll 4
            for (int tt = 0; tt < 200; tt++)
                acc += aA[th * 200 + tt] * vp[(size_t)tt * ED];
            red2[th * 128 + dl] = acc;
            __syncthreads();
            if (tid < 128) {
                float s = red2[tid] + red2[128 + tid];
                g_ctx[b * ED + qq * 128 + tid] = s;
                c_out[((size_t)b * TDEC + t) * ED + qq * 128 + tid] = s;
            }
        }
        grid_sync();
    }
}

// ---------------- prep kernels ----------------
__global__ void k_zero() {
    int i = blockIdx.x * 256 + threadIdx.x;
    if (i < B * LS) {
        g_h0[0][i] = 0.f; g_h0[1][i] = 0.f;
        g_h1[0][i] = 0.f; g_h1[1][i] = 0.f;
        g_c0[i] = 0.f;    g_c1[i] = 0.f;
    }
    if (i < B * ED)   g_ctx[i] = 0.f;
    if (i < B * TENC) g_align[i] = 0.f;
    if (i < B)        g_flag[i] = 0u;
    if (i == 0) { g_bar_count = 0u; g_bar_gen = 0u; }
}

__global__ void k_prep(const float* __restrict__ ck, const float* __restrict__ cb,
                       const float* __restrict__ Wloc) {
    int i = blockIdx.x * 256 + threadIdx.x;
    if (i < KER * UN) {
        int k = i >> 7, u = i & 127;
        float s = 0.f;
        for (int f = 0; f < FIL; f++) s += ck[k * FIL + f] * Wloc[f * UN + u];
        g_Wc[i] = s;
    }
    if (i < UN) {
        float s = 0.f;
        for (int f = 0; f < FIL; f++) s += cb[f] * Wloc[f * UN + i];
        g_locb[i] = s;
    }
}

// weight transform: concat([W;U]) [kreal,4096] -> hi/lo bf16, layout [cta][ch][n32][k256]
__global__ void k_wt(int layer, const float* __restrict__ W, const float* __restrict__ U,
                     int ksplit, int kreal, int nch) {
    size_t idx = (size_t)blockIdx.x * 256 + threadIdx.x;
    size_t total = (size_t)128 * nch * 32 * 256;
    if (idx >= total) return;
    int kk  = (int)(idx & 255);
    int n   = (int)((idx >> 8) & 31);
    size_t rest = idx >> 13;
    int ch  = (int)(rest % nch);
    int cta = (int)(rest / nch);
    int k   = ch * 256 + kk;
    int col = (n >> 3) * 1024 + cta * 8 + (n & 7);
    float v = 0.f;
    if (k < ksplit)     v = W[(size_t)k * 4096 + col];
    else if (k < kreal) v = U[(size_t)(k - ksplit) * 4096 + col];
    // round-to-nearest-even bf16 split
    unsigned ub = __float_as_uint(v);
    unsigned hi = (ub + 0x7fffu + ((ub >> 16) & 1u)) >> 16;
    float fhi = __uint_as_float(hi << 16);
    float lo = v - fhi;
    unsigned ul = __float_as_uint(lo);
    unsigned lo16 = (ul + 0x7fffu + ((ul >> 16) & 1u)) >> 16;
    if (layer == 0) { g_Wh0[idx] = (unsigned short)hi; g_Wl0[idx] = (unsigned short)lo16; }
    else            { g_Wh1[idx] = (unsigned short)hi; g_Wl1[idx] = (unsigned short)lo16; }
}

// keys = values @ Wm
__global__ void k_keys(const float* __restrict__ values, const float* __restrict__ Wm) {
    int b = blockIdx.x, t0 = blockIdx.y * 50;
    __shared__ float vs[10][ED];
    int u = threadIdx.x;
    for (int g = 0; g < 5; g++) {
        int tb = t0 + g * 10;
        __syncthreads();
        for (int i = u; i < 10 * ED; i += 128) {
            int tt = i >> 9, d = i & 511;
            vs[tt][d] = values[((size_t)b * TENC + tb + tt) * ED + d];
        }
        __syncthreads();
        float acc[10];
        #pragma unroll
        for (int tt = 0; tt < 10; tt++) acc[tt] = 0.f;
        for (int d = 0; d < ED; d++) {
            float w = Wm[d * UN + u];
            #pragma unroll
            for (int tt = 0; tt < 10; tt++) acc[tt] += vs[tt][d] * w;
        }
        #pragma unroll
        for (int tt = 0; tt < 10; tt++)
            g_keys[((size_t)b * TENC + tb + tt) * UN + u] = acc[tt];
    }
}

// ---------------- launch ----------------
extern "C" void kernel_launch(void* const* d_in, const int* in_sizes, int n_in,
                              void* d_out, int out_size) {
    const float* values = (const float*)d_in[0];
    const float* dec    = (const float*)d_in[1];
    const float* Wm     = (const float*)d_in[2];
    const float* Wq     = (const float*)d_in[3];
    const float* convk  = (const float*)d_in[4];
    const float* convb  = (const float*)d_in[5];
    const float* Wloc   = (const float*)d_in[6];
    const float* v_a    = (const float*)d_in[7];
    const float* b_a    = (const float*)d_in[8];
    const float* W0     = (const float*)d_in[9];
    const float* U0     = (const float*)d_in[10];
    const float* b0     = (const float*)d_in[11];
    const float* W1     = (const float*)d_in[12];
    const float* U1     = (const float*)d_in[13];
    const float* b1     = (const float*)d_in[14];

    float* out   = (float*)d_out;
    float* c_out = out;                              // [B, TDEC, ED]
    float* e_out = out + (size_t)B * TDEC * ED;      // [B, TDEC, TENC]

    static int smem_set = 0;
    if (!smem_set) {
        cudaFuncSetAttribute(k_persist, cudaFuncAttributeMaxDynamicSharedMemorySize, SMEM_TOTAL);
        smem_set = 1;
    }

    k_zero<<<128, 256>>>();
    k_prep<<<16, 256>>>(convk, convb, Wloc);
    {
        unsigned g0 = (unsigned)(((size_t)128 * NCH0 * 32 * 256 + 255) / 256);
        unsigned g1 = (unsigned)(((size_t)128 * NCH1 * 32 * 256 + 255) / 256);
        k_wt<<<g0, 256>>>(0, W0, U0, DD + ED, K0REAL, NCH0);
        k_wt<<<g1, 256>>>(1, W1, U1, LS, 2 * LS, NCH1);
    }
    k_keys<<<dim3(B, 8), 128>>>(values, Wm);

    k_persist<<<NCTA, 256, SMEM_TOTAL>>>(dec, values, Wq, v_a, b_a, b0, b1, e_out, c_out);
}

// round 4
// speedup vs baseline: 3.2715x; 1.7704x over previous
#include <cuda_runtime.h>
#include <cuda_bf16.h>
#include <math.h>
#include <stdint.h>

#define NCTA 128
#define B    32
#define TENC 400
#define ED   512
#define TDEC 800
#define DD   80
#define LS   1024
#define UN   128
#define KER  31
#define FIL  32
#define NCH0 7
#define NCH1 8
#define K0REAL 1616
#define SROWB 528            // bytes per smem/global row (264 bf16)
#define ROWE  264
#define CHE   (32 * ROWE)    // 8448 elems per chunk tile
#define CHB   16896          // bytes per chunk tile
#define BUFB  (4 * CHB)      // 67584 bytes per pipeline stage

// ---- smem offsets ----
#define OFF_ZSM   135168
#define OFF_MBAR  143616
#define OFF_AS    143648
#define OFF_SPART 144176
#define OFF_SS    150576
#define OFF_AA    152176
#define OFF_RED   153776
#define OFF_RED2  154800
#define SMEM_TOTAL 158896

typedef unsigned short u16;

// ---------------- device state ----------------
__device__ __align__(16) u16 g_Wh0[128 * NCH0 * CHE];
__device__ __align__(16) u16 g_Wl0[128 * NCH0 * CHE];
__device__ __align__(16) u16 g_Wh1[128 * NCH1 * CHE];
__device__ __align__(16) u16 g_Wl1[128 * NCH1 * CHE];
__device__ __align__(16) u16 g_x0h[2][NCH0 * CHE];
__device__ __align__(16) u16 g_x0l[2][NCH0 * CHE];
__device__ __align__(16) u16 g_x1h[2][NCH1 * CHE];
__device__ __align__(16) u16 g_x1l[2][NCH1 * CHE];
__device__ __align__(16) u16 g_dech[B * TDEC * DD];
__device__ __align__(16) u16 g_decl[B * TDEC * DD];
__device__ float g_keys[B * TENC * UN];
__device__ float g_h1f[B * LS];
__device__ float g_c0[B * LS];
__device__ float g_c1[B * LS];
__device__ float g_align[B * TENC];
__device__ float g_scores[B * TENC];
__device__ float g_pqp[B * 8 * UN];
__device__ float g_Wc[KER * UN];
__device__ float g_locb[UN];
__device__ unsigned g_flag[B];
__device__ unsigned g_flag2[B];
__device__ unsigned g_bar_count;
__device__ volatile unsigned g_bar_gen;

// ---------------- helpers ----------------
__device__ __forceinline__ void bsplit(float v, u16& h, u16& l) {
    __nv_bfloat16 hb = __float2bfloat16(v);
    float rh = __bfloat162float(hb);
    __nv_bfloat16 lb = __float2bfloat16(v - rh);
    h = *(u16*)&hb; l = *(u16*)&lb;
}

__device__ __forceinline__ void bulk(uint32_t dst, const void* src, uint32_t bytes, uint32_t mb) {
    asm volatile("cp.async.bulk.shared::cta.global.mbarrier::complete_tx::bytes [%0], [%1], %2, [%3];"
                 :: "r"(dst), "l"(src), "r"(bytes), "r"(mb) : "memory");
}
__device__ __forceinline__ void mbar_init(uint32_t mb, uint32_t cnt) {
    asm volatile("mbarrier.init.shared.b64 [%0], %1;" :: "r"(mb), "r"(cnt) : "memory");
}
__device__ __forceinline__ void mbar_expect(uint32_t mb, uint32_t bytes) {
    asm volatile("mbarrier.arrive.expect_tx.shared.b64 _, [%0], %1;" :: "r"(mb), "r"(bytes) : "memory");
}
__device__ __forceinline__ void mbar_wait(uint32_t mb, uint32_t phase) {
    asm volatile("{\n\t.reg .pred P;\n"
                 "W%=:\n\tmbarrier.try_wait.parity.shared.b64 P, [%0], %1;\n"
                 "\t@P bra D%=;\n\tbra W%=;\nD%=:\n\t}"
                 :: "r"(mb), "r"(phase) : "memory");
}
__device__ __forceinline__ void ldsm4(uint32_t a, uint32_t& r0, uint32_t& r1,
                                      uint32_t& r2, uint32_t& r3) {
    asm volatile("ldmatrix.sync.aligned.m8n8.x4.shared.b16 {%0,%1,%2,%3}, [%4];"
                 : "=r"(r0), "=r"(r1), "=r"(r2), "=r"(r3) : "r"(a));
}
__device__ __forceinline__ void ldsm2(uint32_t a, uint32_t& r0, uint32_t& r1) {
    asm volatile("ldmatrix.sync.aligned.m8n8.x2.shared.b16 {%0,%1}, [%2];"
                 : "=r"(r0), "=r"(r1) : "r"(a));
}
__device__ __forceinline__ void mma16816(float* c, uint32_t a0, uint32_t a1,
                                         uint32_t a2, uint32_t a3,
                                         uint32_t b0, uint32_t b1) {
    asm volatile("mma.sync.aligned.m16n8k16.row.col.f32.bf16.bf16.f32 "
                 "{%0,%1,%2,%3},{%4,%5,%6,%7},{%8,%9},{%0,%1,%2,%3};"
                 : "+f"(c[0]), "+f"(c[1]), "+f"(c[2]), "+f"(c[3])
                 : "r"(a0), "r"(a1), "r"(a2), "r"(a3), "r"(b0), "r"(b1));
}

__device__ __forceinline__ float sigf(float x) { return 1.f / (1.f + expf(-x)); }

__device__ __forceinline__ void grid_sync() {
    __threadfence();
    __syncthreads();
    if (threadIdx.x == 0) {
        unsigned gen = g_bar_gen;
        if (atomicAdd(&g_bar_count, 1u) == NCTA - 1) {
            g_bar_count = 0;
            __threadfence();
            g_bar_gen = gen + 1;
        } else {
            while (g_bar_gen == gen) __nanosleep(32);
        }
    }
    __syncthreads();
    __threadfence();
}

// ---------------- chunk issue ----------------
template <int NCH>
__device__ __forceinline__ void issue_chunk(uint32_t smbase, int cta, long lc, int ch,
        const u16* Wh, const u16* Wl, const u16* Xh, const u16* Xl) {
    uint32_t s = (uint32_t)(lc & 1);
    uint32_t buf = smbase + s * BUFB;
    uint32_t mb  = smbase + OFF_MBAR + s * 8;
    mbar_expect(mb, 4 * CHB);
    const u16* wh = Wh + (size_t)(cta * NCH + ch) * CHE;
    const u16* wl = Wl + (size_t)(cta * NCH + ch) * CHE;
    const u16* xh = Xh + (size_t)ch * CHE;
    const u16* xl = Xl + (size_t)ch * CHE;
    bulk(buf,           wh, CHB, mb);
    bulk(buf + CHB,     wl, CHB, mb);
    bulk(buf + 2 * CHB, xh, CHB, mb);
    bulk(buf + 3 * CHB, xl, CHB, mb);
}

// ---------------- one LSTM layer ----------------
template <int L, int NCH>
__device__ void lstm_layer(char* sm, uint32_t smbase, int cta, int tid, long& lc,
        const u16* Wh, const u16* Wl, const u16* Xh, const u16* Xl,
        u16* Y1h, u16* Y1l,           // bf16 h dest (primary)
        u16* Y0h, u16* Y0l,           // L0 only: next-step x0 slot
        float* __restrict__ c_state, const float* __restrict__ bias) {
    int lane = tid & 31, warp = tid >> 5;
    int nt = warp & 3, kh = warp >> 2, n0 = nt * 8;
    uint32_t aoff = (uint32_t)((lane & 15) * SROWB + (lane >> 4) * 16 + kh * 256);
    uint32_t boff = (uint32_t)((n0 + (lane & 7)) * SROWB + ((lane >> 3) & 1) * 16 + kh * 256);

    float c0a[4] = {0.f, 0.f, 0.f, 0.f};
    float c1a[4] = {0.f, 0.f, 0.f, 0.f};

    if (tid == 0) {
        issue_chunk<NCH>(smbase, cta, lc, 0, Wh, Wl, Xh, Xl);
        issue_chunk<NCH>(smbase, cta, lc + 1, 1, Wh, Wl, Xh, Xl);
    }
    for (int ch = 0; ch < NCH; ch++) {
        uint32_t s = (uint32_t)(lc & 1), ph = (uint32_t)((lc >> 1) & 1);
        mbar_wait(smbase + OFF_MBAR + s * 8, ph);
        uint32_t wh32 = smbase + s * BUFB;
        uint32_t wl32 = wh32 + CHB, xh32 = wh32 + 2 * CHB, xl32 = wh32 + 3 * CHB;
        #pragma unroll
        for (int kk = 0; kk < 8; kk++) {
            uint32_t kb = kk * 32;
            uint32_t b0, b1, f0, f1;
            ldsm2(wh32 + boff + kb, b0, b1);
            ldsm2(wl32 + boff + kb, f0, f1);
            uint32_t a0, a1, a2, a3, e0, e1, e2, e3;
            ldsm4(xh32 + aoff + kb, a0, a1, a2, a3);
            ldsm4(xl32 + aoff + kb, e0, e1, e2, e3);
            mma16816(c0a, a0, a1, a2, a3, b0, b1);
            mma16816(c0a, a0, a1, a2, a3, f0, f1);
            mma16816(c0a, e0, e1, e2, e3, b0, b1);
            ldsm4(xh32 + aoff + kb + 16 * SROWB, a0, a1, a2, a3);
            ldsm4(xl32 + aoff + kb + 16 * SROWB, e0, e1, e2, e3);
            mma16816(c1a, a0, a1, a2, a3, b0, b1);
            mma16816(c1a, a0, a1, a2, a3, f0, f1);
            mma16816(c1a, e0, e1, e2, e3, b0, b1);
        }
        __syncthreads();
        if (tid == 0 && ch + 2 < NCH)
            issue_chunk<NCH>(smbase, cta, lc + 2, ch + 2, Wh, Wl, Xh, Xl);
        lc++;
    }

    float* zsm = (float*)(sm + OFF_ZSM);
    {
        int r = lane >> 2, cp = (lane & 3) * 2;
        float* zz = zsm + kh * (32 * 33);
        zz[r * 33 + n0 + cp]            = c0a[0];
        zz[r * 33 + n0 + cp + 1]        = c0a[1];
        zz[(r + 8) * 33 + n0 + cp]      = c0a[2];
        zz[(r + 8) * 33 + n0 + cp + 1]  = c0a[3];
        zz[(16 + r) * 33 + n0 + cp]     = c1a[0];
        zz[(16 + r) * 33 + n0 + cp + 1] = c1a[1];
        zz[(24 + r) * 33 + n0 + cp]     = c1a[2];
        zz[(24 + r) * 33 + n0 + cp + 1] = c1a[3];
    }
    __syncthreads();
    {
        int j = tid >> 5, b = tid & 31;
        int u = cta * 8 + j;
        float z[4];
        #pragma unroll
        for (int g = 0; g < 4; g++) {
            int n = g * 8 + j;
            z[g] = zsm[b * 33 + n] + zsm[32 * 33 + b * 33 + n] + bias[g * 1024 + u];
        }
        float co = c_state[b * LS + u];
        float cn = sigf(z[1]) * co + sigf(z[0]) * tanhf(z[2]);
        c_state[b * LS + u] = cn;
        float h = sigf(z[3]) * tanhf(cn);
        u16 hh, ll;
        bsplit(h, hh, ll);
        int k1 = (L == 0) ? u : (1024 + u);
        size_t o1 = ((size_t)(k1 >> 8) * 32 + b) * ROWE + (k1 & 255);
        Y1h[o1] = hh; Y1l[o1] = ll;
        if (L == 0) {
            int k0 = 592 + u;
            size_t o0 = ((size_t)(k0 >> 8) * 32 + b) * ROWE + (k0 & 255);
            Y0h[o0] = hh; Y0l[o0] = ll;
        } else {
            g_h1f[b * LS + u] = h;
        }
    }
}

// ---------------- persistent kernel ----------------
__global__ void __launch_bounds__(256, 1) k_persist(
        const float* __restrict__ values, const float* __restrict__ Wq,
        const float* __restrict__ v_a, const float* __restrict__ b_a,
        const float* __restrict__ bias0, const float* __restrict__ bias1,
        float* __restrict__ e_out, float* __restrict__ c_out) {
    extern __shared__ char sm[];
    uint32_t smbase = (uint32_t)__cvta_generic_to_shared(sm);
    int cta = blockIdx.x, tid = threadIdx.x;

    if (tid == 0) {
        mbar_init(smbase + OFF_MBAR, 1);
        mbar_init(smbase + OFF_MBAR + 8, 1);
    }
    __syncthreads();

    long lc = 0;
    for (int t = 0; t < TDEC; t++) {
        int pr = t & 1, cu = pr ^ 1;

        lstm_layer<0, NCH0>(sm, smbase, cta, tid, lc,
            g_Wh0, g_Wl0, g_x0h[pr], g_x0l[pr],
            g_x1h[pr], g_x1l[pr], g_x0h[cu], g_x0l[cu], g_c0, bias0);
        grid_sync();
        lstm_layer<1, NCH1>(sm, smbase, cta, tid, lc,
            g_Wh1, g_Wl1, g_x1h[pr], g_x1l[pr],
            g_x1h[cu], g_x1l[cu], (u16*)0, (u16*)0, g_c1, bias1);
        grid_sync();

        // ---- P3: partial pq (k-split) + location conv + scores ----
        {
            int b = cta >> 2, qq = cta & 3, t0 = qq * 100;
            int u = tid & 127, half = tid >> 7;
            float* aS = (float*)(sm + OFF_AS);
            float* spart = (float*)(sm + OFF_SPART);
            for (int i = tid; i < 130; i += 256) {
                int tg = t0 - 15 + i;
                aS[i] = (tg >= 0 && tg < TENC) ? __ldcg(&g_align[b * TENC + tg]) : 0.f;
            }
            {
                int k0 = qq * 256 + half * 128;
                const float* hb = g_h1f + b * LS + k0;
                const float* wq = Wq + (size_t)k0 * UN + u;
                float acc = 0.f;
                #pragma unroll 8
                for (int k = 0; k < 128; k++)
                    acc += __ldcg(hb + k) * __ldg(wq + (size_t)k * UN);
                g_pqp[((size_t)b * 8 + qq * 2 + half) * UN + u] = acc;
            }
            __threadfence();
            __syncthreads();
            if (tid == 0) {
                atomicAdd(&g_flag2[b], 1u);
                unsigned tg = 4u * (unsigned)(t + 1);
                while (*((volatile unsigned*)&g_flag2[b]) < tg) __nanosleep(32);
            }
            __syncthreads();
            __threadfence();
            float pqu = b_a[u] + g_locb[u];
            #pragma unroll
            for (int s = 0; s < 8; s++)
                pqu += __ldcg(&g_pqp[((size_t)b * 8 + s) * UN + u]);
            float vau = v_a[u];
            float wc[KER];
            #pragma unroll
            for (int k = 0; k < KER; k++) wc[k] = g_Wc[k * UN + u];
            int wl = (tid >> 5) & 3, lane = tid & 31;
            for (int tt = 0; tt < 50; tt++) {
                int tl = half * 50 + tt;
                float s = __ldg(&g_keys[((size_t)b * TENC + t0 + tl) * UN + u]) + pqu;
                #pragma unroll
                for (int k = 0; k < KER; k++) s += aS[tl + k] * wc[k];
                float r = vau * tanhf(s);
                r += __shfl_down_sync(0xffffffffu, r, 16);
                r += __shfl_down_sync(0xffffffffu, r, 8);
                r += __shfl_down_sync(0xffffffffu, r, 4);
                if (lane < 4) spart[tl * 16 + wl * 4 + lane] = r;
            }
            __syncthreads();
            if (tid < 100) {
                float s = 0.f;
                #pragma unroll
                for (int i = 0; i < 16; i++) s += spart[tid * 16 + i];
                g_scores[b * TENC + t0 + tid] = s;
            }
            __threadfence();
            __syncthreads();
            if (tid == 0) atomicAdd(&g_flag[b], 1u);
        }

        // ---- P4: softmax + outputs + context slice ----
        {
            int b = cta >> 2, qq = cta & 3;
            float* sS = (float*)(sm + OFF_SS);
            float* aA = (float*)(sm + OFF_AA);
            float* red = (float*)(sm + OFF_RED);
            float* red2 = (float*)(sm + OFF_RED2);
            if (tid == 0) {
                unsigned tg = 4u * (unsigned)(t + 1);
                while (*((volatile unsigned*)&g_flag[b]) < tg) __nanosleep(32);
            }
            __syncthreads();
            __threadfence();
            float lm = -1e30f;
            for (int i = tid; i < TENC; i += 256) {
                float v = __ldcg(&g_scores[b * TENC + i]);
                sS[i] = v; lm = fmaxf(lm, v);
            }
            red[tid] = lm; __syncthreads();
            for (int o = 128; o; o >>= 1) { if (tid < o) red[tid] = fmaxf(red[tid], red[tid + o]); __syncthreads(); }
            float m = red[0]; __syncthreads();
            float ls = 0.f;
            for (int i = tid; i < TENC; i += 256) {
                float e = expf(sS[i] - m);
                aA[i] = e; ls += e;
            }
            red[tid] = ls; __syncthreads();
            for (int o = 128; o; o >>= 1) { if (tid < o) red[tid] += red[tid + o]; __syncthreads(); }
            float inv = 1.f / red[0]; __syncthreads();
            for (int i = tid; i < TENC; i += 256) aA[i] *= inv;
            __syncthreads();
            if (qq == 0) {
                for (int i = tid; i < TENC; i += 256) {
                    e_out[((size_t)b * TDEC + t) * TENC + i] = aA[i];
                    g_align[b * TENC + i] += aA[i];
                }
            }
            if (qq == 1 && t + 1 < TDEC && tid < DD) {
                size_t sidx = ((size_t)b * TDEC + (t + 1)) * DD + tid;
                g_x0h[cu][b * ROWE + tid] = g_dech[sidx];
                g_x0l[cu][b * ROWE + tid] = g_decl[sidx];
            }
            // context slice [qq*128, +128)
            int g = tid >> 5, c4 = tid & 31;
            float4 acc = make_float4(0.f, 0.f, 0.f, 0.f);
            const float* vp = values + ((size_t)b * TENC + g * 50) * ED + qq * 128 + c4 * 4;
            #pragma unroll 5
            for (int r = 0; r < 50; r++) {
                float a = aA[g * 50 + r];
                float4 v = *(const float4*)(vp + (size_t)r * ED);
                acc.x += a * v.x; acc.y += a * v.y;
                acc.z += a * v.z; acc.w += a * v.w;
            }
            ((float4*)red2)[g * 32 + c4] = acc;
            __syncthreads();
            if (tid < 128) {
                float s = 0.f;
                #pragma unroll
                for (int gg = 0; gg < 8; gg++) s += red2[gg * 128 + tid];
                int d = qq * 128 + tid;
                c_out[((size_t)b * TDEC + t) * ED + d] = s;
                int kk = 80 + d;
                u16 hh, ll;
                bsplit(s, hh, ll);
                size_t xo = ((size_t)(kk >> 8) * 32 + b) * ROWE + (kk & 255);
                g_x0h[cu][xo] = hh; g_x0l[cu][xo] = ll;
            }
        }
        grid_sync();
    }
}

// ---------------- prep kernels ----------------
__global__ void k_init(const float* __restrict__ dec, const float* __restrict__ ck,
                       const float* __restrict__ cb, const float* __restrict__ Wloc) {
    int gid = blockIdx.x * 256 + threadIdx.x;
    int stride = gridDim.x * 256;
    for (int i = gid; i < KER * UN; i += stride) {
        int k = i >> 7, u = i & 127;
        float s = 0.f;
        for (int f = 0; f < FIL; f++) s += ck[k * FIL + f] * Wloc[f * UN + u];
        g_Wc[i] = s;
    }
    for (int i = gid; i < UN; i += stride) {
        float s = 0.f;
        for (int f = 0; f < FIL; f++) s += cb[f] * Wloc[f * UN + i];
        g_locb[i] = s;
    }
    for (int i = gid; i < B * LS; i += stride) { g_c0[i] = 0.f; g_c1[i] = 0.f; }
    for (int i = gid; i < B * TENC; i += stride) g_align[i] = 0.f;
    for (int i = gid; i < B; i += stride) { g_flag[i] = 0u; g_flag2[i] = 0u; }
    if (gid == 0) { g_bar_count = 0u; g_bar_gen = 0u; }
    for (int i = gid; i < 2 * NCH0 * CHE; i += stride) {
        int par = i / (NCH0 * CHE), r = i % (NCH0 * CHE);
        int ch = r / CHE, rr = r % CHE;
        int b = rr / ROWE, kk = rr % ROWE;
        float v = 0.f;
        if (par == 0 && ch == 0 && kk < DD) v = dec[(size_t)b * TDEC * DD + kk];
        u16 hh, ll; bsplit(v, hh, ll);
        g_x0h[par][r] = hh; g_x0l[par][r] = ll;
    }
    for (int i = gid; i < 2 * NCH1 * CHE; i += stride) {
        int par = i / (NCH1 * CHE), r = i % (NCH1 * CHE);
        g_x1h[par][r] = 0; g_x1l[par][r] = 0;
    }
}

__global__ void k_dec(const float* __restrict__ dec) {
    size_t i = (size_t)blockIdx.x * 256 + threadIdx.x;
    if (i >= (size_t)B * TDEC * DD) return;
    u16 hh, ll; bsplit(dec[i], hh, ll);
    g_dech[i] = hh; g_decl[i] = ll;
}

__global__ void k_wt(int layer, const float* __restrict__ W, const float* __restrict__ U,
                     int ksplit, int kreal, int nch) {
    size_t idx = (size_t)blockIdx.x * 256 + threadIdx.x;
    size_t total = (size_t)128 * nch * CHE;
    if (idx >= total) return;
    int kk = (int)(idx % ROWE);
    size_t t1 = idx / ROWE;
    int n = (int)(t1 & 31);
    size_t t2 = t1 >> 5;
    int ch = (int)(t2 % nch);
    int cta = (int)(t2 / nch);
    float v = 0.f;
    if (kk < 256) {
        int k = ch * 256 + kk;
        int col = (n >> 3) * 1024 + cta * 8 + (n & 7);
        if (k < ksplit)      v = W[(size_t)k * 4096 + col];
        else if (k < kreal)  v = U[(size_t)(k - ksplit) * 4096 + col];
    }
    u16 hh, ll; bsplit(v, hh, ll);
    if (layer == 0) { g_Wh0[idx] = hh; g_Wl0[idx] = ll; }
    else            { g_Wh1[idx] = hh; g_Wl1[idx] = ll; }
}

__global__ void k_keys(const float* __restrict__ values, const float* __restrict__ Wm) {
    int b = blockIdx.x, t0 = blockIdx.y * 50;
    __shared__ float vs[10][ED];
    int u = threadIdx.x;
    for (int g = 0; g < 5; g++) {
        int tb = t0 + g * 10;
        __syncthreads();
        for (int i = u; i < 10 * ED; i += 128) {
            int tt = i >> 9, d = i & 511;
            vs[tt][d] = values[((size_t)b * TENC + tb + tt) * ED + d];
        }
        __syncthreads();
        float acc[10];
        #pragma unroll
        for (int tt = 0; tt < 10; tt++) acc[tt] = 0.f;
        for (int d = 0; d < ED; d++) {
            float w = Wm[d * UN + u];
            #pragma unroll
            for (int tt = 0; tt < 10; tt++) acc[tt] += vs[tt][d] * w;
        }
        #pragma unroll
        for (int tt = 0; tt < 10; tt++)
            g_keys[((size_t)b * TENC + tb + tt) * UN + u] = acc[tt];
    }
}

// ---------------- launch ----------------
extern "C" void kernel_launch(void* const* d_in, const int* in_sizes, int n_in,
                              void* d_out, int out_size) {
    const float* values = (const float*)d_in[0];
    const float* dec    = (const float*)d_in[1];
    const float* Wm     = (const float*)d_in[2];
    const float* Wq     = (const float*)d_in[3];
    const float* convk  = (const float*)d_in[4];
    const float* convb  = (const float*)d_in[5];
    const float* Wloc   = (const float*)d_in[6];
    const float* v_a    = (const float*)d_in[7];
    const float* b_a    = (const float*)d_in[8];
    const float* W0     = (const float*)d_in[9];
    const float* U0     = (const float*)d_in[10];
    const float* b0     = (const float*)d_in[11];
    const float* W1     = (const float*)d_in[12];
    const float* U1     = (const float*)d_in[13];
    const float* b1     = (const float*)d_in[14];

    float* out   = (float*)d_out;
    float* c_out = out;                              // [B, TDEC, ED]
    float* e_out = out + (size_t)B * TDEC * ED;      // [B, TDEC, TENC]

    static int smem_set = 0;
    if (!smem_set) {
        cudaFuncSetAttribute(k_persist, cudaFuncAttributeMaxDynamicSharedMemorySize, SMEM_TOTAL);
        smem_set = 1;
    }

    k_init<<<512, 256>>>(dec, convk, convb, Wloc);
    k_dec<<<(B * TDEC * DD + 255) / 256, 256>>>(dec);
    k_wt<<<(unsigned)(((size_t)128 * NCH0 * CHE + 255) / 256), 256>>>(0, W0, U0, DD + ED, K0REAL, NCH0);
    k_wt<<<(unsigned)(((size_t)128 * NCH1 * CHE + 255) / 256), 256>>>(1, W1, U1, LS, 2 * LS, NCH1);
    k_keys<<<dim3(B, 8), 128>>>(values, Wm);

    k_persist<<<NCTA, 256, SMEM_TOTAL>>>(values, Wq, v_a, b_a, b0, b1, e_out, c_out);
}